// round 1
// baseline (speedup 1.0000x reference)
#include <cuda_runtime.h>
#include <math.h>

// Problem constants
#define BATCH 4
#define CIN   256
#define HW    4096
#define DIM   64

// Scratch: q, k, v, sa stored as [B][HW][D] (row = pixel, d contiguous)
__device__ float g_q[BATCH * HW * DIM];
__device__ float g_k[BATCH * HW * DIM];
__device__ float g_v[BATCH * HW * DIM];
__device__ float g_sa[BATCH * HW * DIM];

// ---------------------------------------------------------------------------
// Kernel 1: QKV projections.  out[d, n] = sum_c w[d,c] * x[c,n] + bias[d]
// Stored transposed as out[(b*HW + n)*64 + d].
// grid: (HW/64, B, 3 projections), block: 256 threads (16x16), 4x4 micro-tile.
// ---------------------------------------------------------------------------
__global__ __launch_bounds__(256) void qkv_kernel(
    const float* __restrict__ x,
    const float* __restrict__ wq, const float* __restrict__ bq,
    const float* __restrict__ wk, const float* __restrict__ bk,
    const float* __restrict__ wv, const float* __restrict__ bv)
{
    __shared__ float w_t[64 * 64];  // [c_local][d]   (transposed weight chunk)
    __shared__ float x_s[64 * 64];  // [c_local][n_local]

    const int p  = blockIdx.z;
    const float* w    = (p == 0) ? wq : ((p == 1) ? wk : wv);
    const float* bias = (p == 0) ? bq : ((p == 1) ? bk : bv);
    float* out        = (p == 0) ? g_q : ((p == 1) ? g_k : g_v);

    const int b  = blockIdx.y;
    const int n0 = blockIdx.x * 64;
    const int tid = threadIdx.x;
    const int tx = tid & 15;
    const int ty = tid >> 4;

    float acc[4][4];
#pragma unroll
    for (int r = 0; r < 4; r++)
#pragma unroll
        for (int c = 0; c < 4; c++) acc[r][c] = 0.0f;

    for (int kc = 0; kc < 4; kc++) {
        // load weight chunk [64 d][64 c] -> w_t[c][d], and x chunk [64 c][64 n]
#pragma unroll
        for (int r = 0; r < 4; r++) {
            int row  = (tid >> 4) + r * 16;      // 0..63
            int col4 = (tid & 15) * 4;
            float4 wv4 = *(const float4*)&w[row * CIN + kc * 64 + col4];
            w_t[(col4 + 0) * 64 + row] = wv4.x;
            w_t[(col4 + 1) * 64 + row] = wv4.y;
            w_t[(col4 + 2) * 64 + row] = wv4.z;
            w_t[(col4 + 3) * 64 + row] = wv4.w;
            float4 xv4 = *(const float4*)&x[(b * CIN + kc * 64 + row) * HW + n0 + col4];
            *(float4*)&x_s[row * 64 + col4] = xv4;
        }
        __syncthreads();

#pragma unroll 16
        for (int kk = 0; kk < 64; kk++) {
            float4 a4 = *(const float4*)&w_t[kk * 64 + ty * 4];
            float4 b4 = *(const float4*)&x_s[kk * 64 + tx * 4];
            float ar[4] = {a4.x, a4.y, a4.z, a4.w};
            float br[4] = {b4.x, b4.y, b4.z, b4.w};
#pragma unroll
            for (int r = 0; r < 4; r++)
#pragma unroll
                for (int c = 0; c < 4; c++) acc[r][c] += ar[r] * br[c];
        }
        __syncthreads();
    }

    float bias4[4];
#pragma unroll
    for (int r = 0; r < 4; r++) bias4[r] = bias[ty * 4 + r];

#pragma unroll
    for (int i = 0; i < 4; i++) {
        int n = n0 + tx * 4 + i;
        float4 o4;
        o4.x = acc[0][i] + bias4[0];
        o4.y = acc[1][i] + bias4[1];
        o4.z = acc[2][i] + bias4[2];
        o4.w = acc[3][i] + bias4[3];
        *(float4*)&out[(b * HW + n) * DIM + ty * 4] = o4;
    }
}

// ---------------------------------------------------------------------------
// Kernel 2: fused attention (flash style, fp32).
// grid: (HW/64 query tiles, B), block 256 (16x16), BM=BN=64, 4x4 micro-tiles.
// Dynamic smem: q_t[d][i] + k_t[d][j] + p_s[i][j] + v_s[j][d] = 64KB.
// ---------------------------------------------------------------------------
__global__ __launch_bounds__(256, 2) void attn_kernel()
{
    extern __shared__ float sm[];
    float* q_t = sm;           // [d][i]   4096
    float* k_t = sm + 4096;    // [d][j]   4096
    float* p_s = sm + 8192;    // [i][j]   4096
    float* v_s = sm + 12288;   // [j][d]   4096

    const int b  = blockIdx.y;
    const int i0 = blockIdx.x * 64;
    const int tid = threadIdx.x;
    const int tx = tid & 15;
    const int ty = tid >> 4;

    // Load Q tile transposed: q_t[d][i_local]
#pragma unroll
    for (int r = 0; r < 4; r++) {
        int row  = (tid >> 4) + r * 16;
        int col4 = (tid & 15) * 4;
        float4 q4 = *(const float4*)&g_q[(b * HW + i0 + row) * DIM + col4];
        q_t[(col4 + 0) * 64 + row] = q4.x;
        q_t[(col4 + 1) * 64 + row] = q4.y;
        q_t[(col4 + 2) * 64 + row] = q4.z;
        q_t[(col4 + 3) * 64 + row] = q4.w;
    }

    float o[4][4];
    float m[4], l[4];
#pragma unroll
    for (int r = 0; r < 4; r++) {
        m[r] = -1e30f;
        l[r] = 0.0f;
#pragma unroll
        for (int c = 0; c < 4; c++) o[r][c] = 0.0f;
    }
    __syncthreads();

    for (int jt = 0; jt < HW / 64; jt++) {
        const int j0 = jt * 64;
        // Load K tile transposed (k_t[d][j]) and V tile natural (v_s[j][d])
#pragma unroll
        for (int r = 0; r < 4; r++) {
            int row  = (tid >> 4) + r * 16;     // j local
            int col4 = (tid & 15) * 4;          // d
            float4 k4 = *(const float4*)&g_k[(b * HW + j0 + row) * DIM + col4];
            k_t[(col4 + 0) * 64 + row] = k4.x;
            k_t[(col4 + 1) * 64 + row] = k4.y;
            k_t[(col4 + 2) * 64 + row] = k4.z;
            k_t[(col4 + 3) * 64 + row] = k4.w;
            float4 v4 = *(const float4*)&g_v[(b * HW + j0 + row) * DIM + col4];
            *(float4*)&v_s[row * 64 + col4] = v4;
        }
        __syncthreads();

        // S = Q^T K  (per-thread 4x4 tile)
        float s[4][4];
#pragma unroll
        for (int r = 0; r < 4; r++)
#pragma unroll
            for (int c = 0; c < 4; c++) s[r][c] = 0.0f;

#pragma unroll 16
        for (int d = 0; d < 64; d++) {
            float4 qa = *(const float4*)&q_t[d * 64 + ty * 4];
            float4 ka = *(const float4*)&k_t[d * 64 + tx * 4];
            float qr[4] = {qa.x, qa.y, qa.z, qa.w};
            float kr[4] = {ka.x, ka.y, ka.z, ka.w};
#pragma unroll
            for (int r = 0; r < 4; r++)
#pragma unroll
                for (int c = 0; c < 4; c++) s[r][c] += qr[r] * kr[c];
        }

        // online softmax (rows owned by 16 lanes within a half-warp)
#pragma unroll
        for (int r = 0; r < 4; r++) {
            float rm = fmaxf(fmaxf(s[r][0], s[r][1]), fmaxf(s[r][2], s[r][3]));
            rm = fmaxf(rm, __shfl_xor_sync(0xffffffffu, rm, 8));
            rm = fmaxf(rm, __shfl_xor_sync(0xffffffffu, rm, 4));
            rm = fmaxf(rm, __shfl_xor_sync(0xffffffffu, rm, 2));
            rm = fmaxf(rm, __shfl_xor_sync(0xffffffffu, rm, 1));
            float mn = fmaxf(m[r], rm);
            float alpha = __expf(m[r] - mn);
            float p0 = __expf(s[r][0] - mn);
            float p1 = __expf(s[r][1] - mn);
            float p2 = __expf(s[r][2] - mn);
            float p3 = __expf(s[r][3] - mn);
            float rs = (p0 + p1) + (p2 + p3);
            rs += __shfl_xor_sync(0xffffffffu, rs, 8);
            rs += __shfl_xor_sync(0xffffffffu, rs, 4);
            rs += __shfl_xor_sync(0xffffffffu, rs, 2);
            rs += __shfl_xor_sync(0xffffffffu, rs, 1);
            l[r] = l[r] * alpha + rs;
            m[r] = mn;
#pragma unroll
            for (int c = 0; c < 4; c++) o[r][c] *= alpha;
            *(float4*)&p_s[(ty * 4 + r) * 64 + tx * 4] = make_float4(p0, p1, p2, p3);
        }
        __syncthreads();

        // O += P * V
#pragma unroll 16
        for (int j = 0; j < 64; j++) {
            float4 v4 = *(const float4*)&v_s[j * 64 + tx * 4];
            float vr[4] = {v4.x, v4.y, v4.z, v4.w};
            float pr[4];
#pragma unroll
            for (int r = 0; r < 4; r++) pr[r] = p_s[(ty * 4 + r) * 64 + j];
#pragma unroll
            for (int r = 0; r < 4; r++)
#pragma unroll
                for (int c = 0; c < 4; c++) o[r][c] += pr[r] * vr[c];
        }
        __syncthreads();
    }

    // normalize + store sa as [n][d]
#pragma unroll
    for (int r = 0; r < 4; r++) {
        float inv = 1.0f / l[r];
        int i = i0 + ty * 4 + r;
        float4 o4;
        o4.x = o[r][0] * inv;
        o4.y = o[r][1] * inv;
        o4.z = o[r][2] * inv;
        o4.w = o[r][3] * inv;
        *(float4*)&g_sa[(b * HW + i) * DIM + tx * 4] = o4;
    }
}

// ---------------------------------------------------------------------------
// Kernel 3: output projection + bias + gamma * out + residual x.
// out[b,c,n] = gamma * (wsa[c,:] . sa[b,n,:] + bsa[c]) + x[b,c,n]
// grid: (HW/64, C/64, B), block 256 (16x16), K=64 single pass.
// ---------------------------------------------------------------------------
__global__ __launch_bounds__(256) void proj_kernel(
    const float* __restrict__ x,
    const float* __restrict__ wsa,
    const float* __restrict__ bsa,
    const float* __restrict__ gamma,
    float* __restrict__ out)
{
    __shared__ float wsa_t[64 * 64];  // [d][c_local]
    __shared__ float sa_t[64 * 64];   // [d][n_local]

    const int b  = blockIdx.z;
    const int cc = blockIdx.y;
    const int n0 = blockIdx.x * 64;
    const int tid = threadIdx.x;
    const int tx = tid & 15;
    const int ty = tid >> 4;

#pragma unroll
    for (int r = 0; r < 4; r++) {
        int row = (tid >> 4) + r * 16;
        int d4  = (tid & 15) * 4;
        float4 w4 = *(const float4*)&wsa[(cc * 64 + row) * DIM + d4];
        wsa_t[(d4 + 0) * 64 + row] = w4.x;
        wsa_t[(d4 + 1) * 64 + row] = w4.y;
        wsa_t[(d4 + 2) * 64 + row] = w4.z;
        wsa_t[(d4 + 3) * 64 + row] = w4.w;
        float4 s4 = *(const float4*)&g_sa[(b * HW + n0 + row) * DIM + d4];
        sa_t[(d4 + 0) * 64 + row] = s4.x;
        sa_t[(d4 + 1) * 64 + row] = s4.y;
        sa_t[(d4 + 2) * 64 + row] = s4.z;
        sa_t[(d4 + 3) * 64 + row] = s4.w;
    }
    __syncthreads();

    float acc[4][4];
#pragma unroll
    for (int r = 0; r < 4; r++)
#pragma unroll
        for (int c = 0; c < 4; c++) acc[r][c] = 0.0f;

#pragma unroll 16
    for (int d = 0; d < 64; d++) {
        float4 a4 = *(const float4*)&wsa_t[d * 64 + ty * 4];
        float4 b4 = *(const float4*)&sa_t[d * 64 + tx * 4];
        float ar[4] = {a4.x, a4.y, a4.z, a4.w};
        float br[4] = {b4.x, b4.y, b4.z, b4.w};
#pragma unroll
        for (int r = 0; r < 4; r++)
#pragma unroll
            for (int c = 0; c < 4; c++) acc[r][c] += ar[r] * br[c];
    }

    const float g = gamma[0];
#pragma unroll
    for (int r = 0; r < 4; r++) {
        int c = cc * 64 + ty * 4 + r;
        float bias = bsa[c];
        int base = (b * CIN + c) * HW + n0 + tx * 4;
        float4 xv = *(const float4*)&x[base];
        float4 o4;
        o4.x = g * (acc[r][0] + bias) + xv.x;
        o4.y = g * (acc[r][1] + bias) + xv.y;
        o4.z = g * (acc[r][2] + bias) + xv.z;
        o4.w = g * (acc[r][3] + bias) + xv.w;
        *(float4*)&out[base] = o4;
    }
}

// ---------------------------------------------------------------------------
extern "C" void kernel_launch(void* const* d_in, const int* in_sizes, int n_in,
                              void* d_out, int out_size)
{
    const float* x     = (const float*)d_in[0];
    const float* wq    = (const float*)d_in[1];
    const float* bq    = (const float*)d_in[2];
    const float* wk    = (const float*)d_in[3];
    const float* bk    = (const float*)d_in[4];
    const float* wv    = (const float*)d_in[5];
    const float* bv    = (const float*)d_in[6];
    const float* wsa   = (const float*)d_in[7];
    const float* bsa   = (const float*)d_in[8];
    const float* gamma = (const float*)d_in[9];
    float* out = (float*)d_out;

    cudaFuncSetAttribute(attn_kernel, cudaFuncAttributeMaxDynamicSharedMemorySize, 65536);

    qkv_kernel<<<dim3(HW / 64, BATCH, 3), 256>>>(x, wq, bq, wk, bk, wv, bv);
    attn_kernel<<<dim3(HW / 64, BATCH), 256, 65536>>>();
    proj_kernel<<<dim3(HW / 64, CIN / 64, BATCH), 256>>>(x, wsa, bsa, gamma, out);
}